// round 4
// baseline (speedup 1.0000x reference)
#include <cuda_runtime.h>
#include <cstdint>

// ---------------------------------------------------------------------------
// EdgeGATv2: N=100000 nodes, E=1600000 edges, IN=128, OUT=64 (H=4 x HD=16),
// EDGE_DIM=32.  Output = [rst (N*64 floats) ; alpha (E*4 floats)].
//
// Passes:
//   k_init      : rst = bias, segmax = -inf(enc), segsum = 0
//   k_nodeproj  : fs = nf @ Wsrc^T, fd = nf @ Wdst^T   (fused, one nf read)
//   k_edge      : per edge: eproj = ef @ We^T (smem GEMV, f32x2), gather
//                 fs[src]+fd[dst], leaky, attn-dot -> logits + atomicMax seg max
//   k_soft      : ex = exp(logit - segmax[dst]) in place; red.v4 segsum
//   k_agg       : alpha = ex/segsum[dst] -> out; red.v4 scatter fs[src]*alpha
// ---------------------------------------------------------------------------

#define NN    100000
#define NE    1600000
#define OUTD  64

typedef unsigned long long u64;

// ---------------- scratch (no allocations allowed) -------------------------
__device__ float g_fs[(size_t)NN * OUTD];     // 25.6 MB
__device__ float g_fd[(size_t)NN * OUTD];     // 25.6 MB
__device__ float g_logit[(size_t)NE * 4];     // 25.6 MB (reused as ex)
__device__ int   g_maxenc[NN * 4];            // 1.6 MB
__device__ float g_sum[NN * 4];               // 1.6 MB

// ---------------- helpers ---------------------------------------------------
__device__ __forceinline__ u64 pack2(float lo, float hi) {
    u64 r; asm("mov.b64 %0, {%1, %2};" : "=l"(r) : "f"(lo), "f"(hi)); return r;
}
__device__ __forceinline__ void fma2(u64& d, u64 a, u64 b) {
    asm("fma.rn.f32x2 %0, %1, %2, %0;" : "+l"(d) : "l"(a), "l"(b));
}
__device__ __forceinline__ float lo32(u64 v) { return __uint_as_float((unsigned)v); }
__device__ __forceinline__ float hi32(u64 v) { return __uint_as_float((unsigned)(v >> 32)); }

// order-preserving float->int encoding for atomicMax
__device__ __forceinline__ int fenc(float f) {
    int i = __float_as_int(f);
    return i >= 0 ? i : (i ^ 0x7fffffff);
}
__device__ __forceinline__ float fdec(int e) {
    return __int_as_float(e >= 0 ? e : (e ^ 0x7fffffff));
}

__device__ __forceinline__ void red_add_v4(float* p, float a, float b, float c, float d) {
    asm volatile("red.global.add.v4.f32 [%0], {%1, %2, %3, %4};"
                 :: "l"(p), "f"(a), "f"(b), "f"(c), "f"(d) : "memory");
}

// ---------------- k_init ----------------------------------------------------
__global__ void k_init(const float* __restrict__ bias, float* __restrict__ rst) {
    int i = blockIdx.x * 256 + threadIdx.x;          // covers NN*64 = 6.4M exactly
    rst[i] = bias[i & 63];
    if (i < NN * 4) { g_maxenc[i] = 0x80000000; g_sum[i] = 0.0f; }
}

// ---------------- k_nodeproj ------------------------------------------------
// 256 threads, 32 nodes/block. smem: Ws[128][64], Wd[128][64] (k-major),
// nfs[32][132] (padded). Thread = (node nl=tid>>3, colgroup cg=tid&7 -> 8 cols)
// computes 8 src + 8 dst outputs with FFMA2.
__global__ __launch_bounds__(256) void k_nodeproj(
    const float* __restrict__ nf, const float* __restrict__ Wsrc,
    const float* __restrict__ Wdst)
{
    extern __shared__ float sm[];
    float* Ws  = sm;                 // 8192 floats
    float* Wd  = sm + 8192;          // 8192 floats
    float* nfs = sm + 16384;         // 32*132 floats
    int tid = threadIdx.x;

    // transpose W into k-major (reads strided through L2 - W is tiny/L2-hot;
    // smem writes coalesced/conflict-free)
    for (int i = tid; i < 8192; i += 256) {
        int k = i >> 6, c = i & 63;
        Ws[i] = Wsrc[c * 128 + k];
        Wd[i] = Wdst[c * 128 + k];
    }
    int n0 = blockIdx.x * 32;
    for (int i = tid; i < 32 * 128; i += 256) {
        int n = i >> 7, k = i & 127;
        nfs[n * 132 + k] = nf[(size_t)(n0 + n) * 128 + k];
    }
    __syncthreads();

    int nl = tid >> 3;               // 0..31
    int cg = tid & 7;                // cols 8cg..8cg+7
    u64 as[4] = {0, 0, 0, 0};
    u64 ad[4] = {0, 0, 0, 0};
    const float* nrow = nfs + nl * 132;
    const u64* Ws2 = (const u64*)Ws;
    const u64* Wd2 = (const u64*)Wd;

    #pragma unroll 8
    for (int k = 0; k < 128; k++) {
        float x = nrow[k];
        u64 xx = pack2(x, x);
        int b = k * 32 + cg * 4;
        fma2(as[0], xx, Ws2[b + 0]); fma2(as[1], xx, Ws2[b + 1]);
        fma2(as[2], xx, Ws2[b + 2]); fma2(as[3], xx, Ws2[b + 3]);
        fma2(ad[0], xx, Wd2[b + 0]); fma2(ad[1], xx, Wd2[b + 1]);
        fma2(ad[2], xx, Wd2[b + 2]); fma2(ad[3], xx, Wd2[b + 3]);
    }
    size_t base = (size_t)(n0 + nl) * 64 + cg * 8;
    u64* os = (u64*)(g_fs + base);
    u64* od = (u64*)(g_fd + base);
    #pragma unroll
    for (int q = 0; q < 4; q++) { os[q] = as[q]; od[q] = ad[q]; }
}

// ---------------- k_edge ----------------------------------------------------
// 256 threads = 256 edges/block. Edge projection as smem GEMV with broadcast
// W reads + transposed/padded edge-feature staging; fused gather+leaky+attn.
__global__ __launch_bounds__(256) void k_edge(
    const float* __restrict__ ef, const float* __restrict__ We,
    const float* __restrict__ attn,
    const int* __restrict__ src, const int* __restrict__ dst)
{
    __shared__ __align__(16) float Wes[32 * 64];    // [k][c]  8 KB
    __shared__ __align__(16) float efs[32 * 257];   // [k][t]  ~32.9 KB, padded
    __shared__ __align__(16) float attns[64];

    int tid = threadIdx.x;
    int e0  = blockIdx.x * 256;

    for (int i = tid; i < 2048; i += 256) {          // We [64][32] -> k-major
        int k = i >> 6, c = i & 63;
        Wes[i] = We[c * 32 + k];
    }
    if (tid < 64) attns[tid] = attn[tid];

    // stage edge_feat transposed: global reads fully coalesced,
    // smem writes bank-spread (4j + i + e_local covers all 32 banks)
    const float4* efg = (const float4*)ef + (size_t)e0 * 8;
    #pragma unroll
    for (int it = 0; it < 8; it++) {
        int idx = it * 256 + tid;
        float4 v = efg[idx];
        int el = idx >> 3, j = idx & 7;
        efs[(4 * j + 0) * 257 + el] = v.x;
        efs[(4 * j + 1) * 257 + el] = v.y;
        efs[(4 * j + 2) * 257 + el] = v.z;
        efs[(4 * j + 3) * 257 + el] = v.w;
    }
    int e = e0 + tid;
    int s = src[e], d = dst[e];
    __syncthreads();

    // eproj: acc[cp] = sum_k ef[k] * (We[k][2cp], We[k][2cp+1])
    u64 acc[32];
    #pragma unroll
    for (int i = 0; i < 32; i++) acc[i] = 0ull;
    const u64* W2 = (const u64*)Wes;
    #pragma unroll 4
    for (int k = 0; k < 32; k++) {
        float x = efs[k * 257 + tid];                // conflict-free: bank (k+t)%32
        u64 xx = pack2(x, x);
        #pragma unroll
        for (int cp = 0; cp < 32; cp++)
            fma2(acc[cp], xx, W2[k * 32 + cp]);      // broadcast
    }

    // gather + leaky + attn dot
    const float4* fsp = (const float4*)g_fs + (size_t)s * 16;
    const float4* fdp = (const float4*)g_fd + (size_t)d * 16;
    const float4* at4 = (const float4*)attns;
    float logit[4] = {0.f, 0.f, 0.f, 0.f};
    #pragma unroll
    for (int i = 0; i < 16; i++) {
        float4 a = fsp[i];
        float4 b = fdp[i];
        float t0 = lo32(acc[2 * i])     + a.x + b.x;
        float t1 = hi32(acc[2 * i])     + a.y + b.y;
        float t2 = lo32(acc[2 * i + 1]) + a.z + b.z;
        float t3 = hi32(acc[2 * i + 1]) + a.w + b.w;
        t0 = fmaxf(t0, 0.2f * t0);                   // leaky_relu
        t1 = fmaxf(t1, 0.2f * t1);
        t2 = fmaxf(t2, 0.2f * t2);
        t3 = fmaxf(t3, 0.2f * t3);
        float4 at = at4[i];
        int h = i >> 2;
        logit[h] += t0 * at.x + t1 * at.y + t2 * at.z + t3 * at.w;
    }

    ((float4*)g_logit)[e] = make_float4(logit[0], logit[1], logit[2], logit[3]);
    #pragma unroll
    for (int h = 0; h < 4; h++)
        atomicMax(&g_maxenc[d * 4 + h], fenc(logit[h]));
}

// ---------------- k_soft ----------------------------------------------------
__global__ __launch_bounds__(256) void k_soft(const int* __restrict__ dst) {
    int e = blockIdx.x * 256 + threadIdx.x;
    int d = dst[e];
    float4 l = ((const float4*)g_logit)[e];
    int4 m = *(const int4*)(g_maxenc + d * 4);
    float4 ex;
    ex.x = __expf(l.x - fdec(m.x));
    ex.y = __expf(l.y - fdec(m.y));
    ex.z = __expf(l.z - fdec(m.z));
    ex.w = __expf(l.w - fdec(m.w));
    ((float4*)g_logit)[e] = ex;
    red_add_v4(g_sum + d * 4, ex.x, ex.y, ex.z, ex.w);
}

// ---------------- k_agg -----------------------------------------------------
__global__ __launch_bounds__(256) void k_agg(
    const int* __restrict__ src, const int* __restrict__ dst,
    float* __restrict__ rst, float* __restrict__ alpha_out)
{
    int e = blockIdx.x * 256 + threadIdx.x;
    int s = src[e], d = dst[e];
    float4 ex = ((const float4*)g_logit)[e];
    float4 sm = *(const float4*)(g_sum + d * 4);
    float4 al;
    al.x = __fdividef(ex.x, sm.x);
    al.y = __fdividef(ex.y, sm.y);
    al.z = __fdividef(ex.z, sm.z);
    al.w = __fdividef(ex.w, sm.w);
    ((float4*)alpha_out)[e] = al;

    const float4* fsp = (const float4*)g_fs + (size_t)s * 16;
    float* rrow = rst + (size_t)d * 64;
    float ah[4] = {al.x, al.y, al.z, al.w};
    #pragma unroll
    for (int i = 0; i < 16; i++) {
        float4 f = fsp[i];
        float a = ah[i >> 2];
        red_add_v4(rrow + i * 4, f.x * a, f.y * a, f.z * a, f.w * a);
    }
}

// ---------------- launch ----------------------------------------------------
extern "C" void kernel_launch(void* const* d_in, const int* in_sizes, int n_in,
                              void* d_out, int out_size) {
    const float* node_feat = (const float*)d_in[0];
    const float* edge_feat = (const float*)d_in[1];
    const float* W_src     = (const float*)d_in[2];
    const float* W_dst     = (const float*)d_in[3];
    const float* W_edge    = (const float*)d_in[4];
    const float* attn      = (const float*)d_in[5];
    const float* bias      = (const float*)d_in[6];
    const int*   src       = (const int*)d_in[7];
    const int*   dst       = (const int*)d_in[8];
    float* rst   = (float*)d_out;                       // [N,64]
    float* alpha = (float*)d_out + (size_t)NN * OUTD;   // [E,4]

    const int NODE_SMEM = (8192 + 8192 + 32 * 132) * 4; // 82432 B
    cudaFuncSetAttribute(k_nodeproj, cudaFuncAttributeMaxDynamicSharedMemorySize,
                         NODE_SMEM);

    k_init<<<NN * 64 / 256, 256>>>(bias, rst);
    k_nodeproj<<<NN / 32, 256, NODE_SMEM>>>(node_feat, W_src, W_dst);
    k_edge<<<NE / 256, 256>>>(edge_feat, W_edge, attn, src, dst);
    k_soft<<<NE / 256, 256>>>(dst);
    k_agg<<<NE / 256, 256>>>(src, dst, rst, alpha);
}

// round 5
// speedup vs baseline: 1.0366x; 1.0366x over previous
#include <cuda_runtime.h>
#include <cstdint>

// ---------------------------------------------------------------------------
// EdgeGATv2: N=100000 nodes, E=1600000 edges, IN=128, OUT=64 (H=4 x HD=16),
// EDGE_DIM=32.  Output = [rst (N*64 floats) ; alpha (E*4 floats)].
// ---------------------------------------------------------------------------

#define NN    100000
#define NE    1600000
#define OUTD  64

typedef unsigned long long u64;

// ---------------- scratch (no allocations allowed) -------------------------
__device__ float g_fs[(size_t)NN * OUTD];     // 25.6 MB
__device__ float g_fd[(size_t)NN * OUTD];     // 25.6 MB
__device__ float g_logit[(size_t)NE * 4];     // 25.6 MB (reused as ex)
__device__ int   g_maxenc[NN * 4];            // 1.6 MB
__device__ float g_sum[NN * 4];               // 1.6 MB

// ---------------- helpers ---------------------------------------------------
__device__ __forceinline__ u64 pack2(float lo, float hi) {
    u64 r; asm("mov.b64 %0, {%1, %2};" : "=l"(r) : "f"(lo), "f"(hi)); return r;
}
__device__ __forceinline__ void fma2(u64& d, u64 a, u64 b) {
    asm("fma.rn.f32x2 %0, %1, %2, %0;" : "+l"(d) : "l"(a), "l"(b));
}
__device__ __forceinline__ float lo32(u64 v) { return __uint_as_float((unsigned)v); }
__device__ __forceinline__ float hi32(u64 v) { return __uint_as_float((unsigned)(v >> 32)); }

// order-preserving float->int encoding for atomicMax
__device__ __forceinline__ int fenc(float f) {
    int i = __float_as_int(f);
    return i >= 0 ? i : (i ^ 0x7fffffff);
}
__device__ __forceinline__ float fdec(int e) {
    return __int_as_float(e >= 0 ? e : (e ^ 0x7fffffff));
}

__device__ __forceinline__ void red_add_v4(float* p, float a, float b, float c, float d) {
    asm volatile("red.global.add.v4.f32 [%0], {%1, %2, %3, %4};"
                 :: "l"(p), "f"(a), "f"(b), "f"(c), "f"(d) : "memory");
}

// ---------------- init (split in two so k_edge lands at launch slot 3) -----
__global__ void k_init_rst(const float* __restrict__ bias, float* __restrict__ rst) {
    int i = blockIdx.x * 256 + threadIdx.x;          // NN*64 = 6.4M exactly
    rst[i] = bias[i & 63];
}
__global__ void k_init_seg() {
    int i = blockIdx.x * 256 + threadIdx.x;
    if (i < NN * 4) { g_maxenc[i] = 0x80000000; g_sum[i] = 0.0f; }
}

// ---------------- k_nodeproj ------------------------------------------------
// 256 threads, 32 nodes/block. smem: Ws[128][64], Wd[128][64] (k-major),
// nfs[32][132] (padded). Thread = (node, 8-col group), FFMA2 along k.
__global__ __launch_bounds__(256) void k_nodeproj(
    const float* __restrict__ nf, const float* __restrict__ Wsrc,
    const float* __restrict__ Wdst)
{
    extern __shared__ float sm[];
    float* Ws  = sm;                 // 8192 floats
    float* Wd  = sm + 8192;          // 8192 floats
    float* nfs = sm + 16384;         // 32*132 floats
    int tid = threadIdx.x;

    for (int i = tid; i < 8192; i += 256) {
        int k = i >> 6, c = i & 63;
        Ws[i] = Wsrc[c * 128 + k];
        Wd[i] = Wdst[c * 128 + k];
    }
    int n0 = blockIdx.x * 32;
    for (int i = tid; i < 32 * 128; i += 256) {
        int n = i >> 7, k = i & 127;
        nfs[n * 132 + k] = nf[(size_t)(n0 + n) * 128 + k];
    }
    __syncthreads();

    int nl = tid >> 3;
    int cg = tid & 7;
    u64 as[4] = {0, 0, 0, 0};
    u64 ad[4] = {0, 0, 0, 0};
    const float* nrow = nfs + nl * 132;
    const u64* Ws2 = (const u64*)Ws;
    const u64* Wd2 = (const u64*)Wd;

    #pragma unroll 8
    for (int k = 0; k < 128; k++) {
        float x = nrow[k];
        u64 xx = pack2(x, x);
        int b = k * 32 + cg * 4;
        fma2(as[0], xx, Ws2[b + 0]); fma2(as[1], xx, Ws2[b + 1]);
        fma2(as[2], xx, Ws2[b + 2]); fma2(as[3], xx, Ws2[b + 3]);
        fma2(ad[0], xx, Wd2[b + 0]); fma2(ad[1], xx, Wd2[b + 1]);
        fma2(ad[2], xx, Wd2[b + 2]); fma2(ad[3], xx, Wd2[b + 3]);
    }
    size_t base = (size_t)(n0 + nl) * 64 + cg * 8;
    u64* os = (u64*)(g_fs + base);
    u64* od = (u64*)(g_fd + base);
    #pragma unroll
    for (int q = 0; q < 4; q++) { os[q] = as[q]; od[q] = ad[q]; }
}

// ---------------- k_edge ----------------------------------------------------
// 512 threads, 256 edges/block. Thread = (head cg = tid>>7, edge-pair
// ep = tid&127 -> edges 2ep, 2ep+1).  acc = 16 u64 (32 regs, spill-proof).
// efs stored transposed [feat r][edge el] with XOR quad-swizzle:
//   col(el, r) = 4*((el>>2) ^ (r>>2)) + (el&3)
// -> staged writes and LDS.64 reads both provably bank-conflict-free.
__global__ __launch_bounds__(512) void k_edge(
    const float* __restrict__ ef, const float* __restrict__ We,
    const float* __restrict__ attn,
    const int* __restrict__ src, const int* __restrict__ dst)
{
    __shared__ __align__(16) float Wes[32 * 64];    // [k][c]  8 KB
    __shared__ __align__(16) float efs[32 * 256];   // swizzled, 32 KB
    __shared__ __align__(16) float attns[64];

    int tid = threadIdx.x;
    int e0  = blockIdx.x * 256;

    for (int i = tid; i < 2048; i += 512) {          // We [64][32] -> k-major
        int k = i >> 6, c = i & 63;
        Wes[i] = We[c * 32 + k];
    }
    if (tid < 64) attns[tid] = attn[tid];

    // stage edge_feat: global float4 reads coalesced; swizzled smem writes
    const float4* efg = (const float4*)ef + (size_t)e0 * 8;
    #pragma unroll
    for (int it = 0; it < 4; it++) {
        int idx = it * 512 + tid;
        float4 v = efg[idx];
        int el = idx >> 3, j = idx & 7;              // features 4j..4j+3
        int col = 4 * ((el >> 2) ^ j) + (el & 3);
        efs[(4 * j + 0) * 256 + col] = v.x;
        efs[(4 * j + 1) * 256 + col] = v.y;
        efs[(4 * j + 2) * 256 + col] = v.z;
        efs[(4 * j + 3) * 256 + col] = v.w;
    }

    int cg = tid >> 7;          // head 0..3 (owns cols 16cg..16cg+15)
    int ep = tid & 127;         // edge pair: edges e0+2ep, e0+2ep+1
    int e  = e0 + 2 * ep;
    int2 s2 = ((const int2*)src)[e >> 1];
    int2 d2 = ((const int2*)dst)[e >> 1];
    __syncthreads();

    // eproj GEMV: acc[i*8+p] = sum_k x_i[k] * We2[k][cg*8+p]
    u64 acc[16];
    #pragma unroll
    for (int i = 0; i < 16; i++) acc[i] = 0ull;
    const u64* W2 = (const u64*)Wes;

    #pragma unroll 4
    for (int k = 0; k < 32; k++) {
        float2 x2 = *(const float2*)&efs[k * 256 + 4 * ((ep >> 1) ^ (k >> 2)) + 2 * (ep & 1)];
        u64 x0 = pack2(x2.x, x2.x);
        u64 x1 = pack2(x2.y, x2.y);
        const u64* wrow = W2 + k * 32 + cg * 8;      // broadcast (cg const/warp)
        #pragma unroll
        for (int p = 0; p < 8; p++) {
            u64 w = wrow[p];
            fma2(acc[p],     x0, w);
            fma2(acc[8 + p], x1, w);
        }
    }

    // gather + leaky + attn dot, per owned edge
    const float4* at4 = (const float4*)(attns + cg * 16);
    int ss[2] = {s2.x, s2.y};
    int dd[2] = {d2.x, d2.y};
    #pragma unroll
    for (int i = 0; i < 2; i++) {
        const float4* fsp = (const float4*)g_fs + (size_t)ss[i] * 16 + cg * 4;
        const float4* fdp = (const float4*)g_fd + (size_t)dd[i] * 16 + cg * 4;
        float lg = 0.f;
        #pragma unroll
        for (int q = 0; q < 4; q++) {
            float4 a = fsp[q];
            float4 b = fdp[q];
            float t0 = lo32(acc[i * 8 + 2 * q])     + a.x + b.x;
            float t1 = hi32(acc[i * 8 + 2 * q])     + a.y + b.y;
            float t2 = lo32(acc[i * 8 + 2 * q + 1]) + a.z + b.z;
            float t3 = hi32(acc[i * 8 + 2 * q + 1]) + a.w + b.w;
            t0 = fmaxf(t0, 0.2f * t0);
            t1 = fmaxf(t1, 0.2f * t1);
            t2 = fmaxf(t2, 0.2f * t2);
            t3 = fmaxf(t3, 0.2f * t3);
            float4 at = at4[q];
            lg += t0 * at.x + t1 * at.y + t2 * at.z + t3 * at.w;
        }
        g_logit[(size_t)(e + i) * 4 + cg] = lg;
        atomicMax(&g_maxenc[dd[i] * 4 + cg], fenc(lg));
    }
}

// ---------------- k_soft ----------------------------------------------------
__global__ __launch_bounds__(256) void k_soft(const int* __restrict__ dst) {
    int e = blockIdx.x * 256 + threadIdx.x;
    int d = dst[e];
    float4 l = ((const float4*)g_logit)[e];
    int4 m = *(const int4*)(g_maxenc + d * 4);
    float4 ex;
    ex.x = __expf(l.x - fdec(m.x));
    ex.y = __expf(l.y - fdec(m.y));
    ex.z = __expf(l.z - fdec(m.z));
    ex.w = __expf(l.w - fdec(m.w));
    ((float4*)g_logit)[e] = ex;
    red_add_v4(g_sum + d * 4, ex.x, ex.y, ex.z, ex.w);
}

// ---------------- k_agg -----------------------------------------------------
__global__ __launch_bounds__(256) void k_agg(
    const int* __restrict__ src, const int* __restrict__ dst,
    float* __restrict__ rst, float* __restrict__ alpha_out)
{
    int e = blockIdx.x * 256 + threadIdx.x;
    int s = src[e], d = dst[e];
    float4 ex = ((const float4*)g_logit)[e];
    float4 sm = *(const float4*)(g_sum + d * 4);
    float4 al;
    al.x = __fdividef(ex.x, sm.x);
    al.y = __fdividef(ex.y, sm.y);
    al.z = __fdividef(ex.z, sm.z);
    al.w = __fdividef(ex.w, sm.w);
    ((float4*)alpha_out)[e] = al;

    const float4* fsp = (const float4*)g_fs + (size_t)s * 16;
    float* rrow = rst + (size_t)d * 64;
    float ah[4] = {al.x, al.y, al.z, al.w};
    #pragma unroll
    for (int i = 0; i < 16; i++) {
        float4 f = fsp[i];
        float a = ah[i >> 2];
        red_add_v4(rrow + i * 4, f.x * a, f.y * a, f.z * a, f.w * a);
    }
}

// ---------------- launch ----------------------------------------------------
extern "C" void kernel_launch(void* const* d_in, const int* in_sizes, int n_in,
                              void* d_out, int out_size) {
    const float* node_feat = (const float*)d_in[0];
    const float* edge_feat = (const float*)d_in[1];
    const float* W_src     = (const float*)d_in[2];
    const float* W_dst     = (const float*)d_in[3];
    const float* W_edge    = (const float*)d_in[4];
    const float* attn      = (const float*)d_in[5];
    const float* bias      = (const float*)d_in[6];
    const int*   src       = (const int*)d_in[7];
    const int*   dst       = (const int*)d_in[8];
    float* rst   = (float*)d_out;                       // [N,64]
    float* alpha = (float*)d_out + (size_t)NN * OUTD;   // [E,4]

    const int NODE_SMEM = (8192 + 8192 + 32 * 132) * 4; // 82432 B
    cudaFuncSetAttribute(k_nodeproj, cudaFuncAttributeMaxDynamicSharedMemorySize,
                         NODE_SMEM);

    k_init_rst<<<NN * 64 / 256, 256>>>(bias, rst);          // slot 0
    k_init_seg<<<(NN * 4 + 255) / 256, 256>>>();            // slot 1
    k_nodeproj<<<NN / 32, 256, NODE_SMEM>>>(node_feat, W_src, W_dst); // slot 2
    k_edge<<<NE / 256, 512>>>(edge_feat, W_edge, attn, src, dst);     // slot 3
    k_soft<<<NE / 256, 256>>>(dst);                         // slot 4
    k_agg<<<NE / 256, 256>>>(src, dst, rst, alpha);         // slot 5
}

// round 6
// speedup vs baseline: 1.8642x; 1.7984x over previous
#include <cuda_runtime.h>
#include <cstdint>

// ---------------------------------------------------------------------------
// EdgeGATv2: N=100000 nodes, E=1600000 edges, IN=128, OUT=64 (H=4 x HD=16),
// EDGE_DIM=32.  Output = [rst (N*64 floats) ; alpha (E*4 floats)].
//
// f32x2 pairing is over EDGES/NODES (not columns): each lane owns output
// columns, W lives in smem duplicated ((w,w) u64) so W reads are dense
// LDS.128, x reads are broadcast LDS.128 feeding 4 edges/nodes at once.
// ---------------------------------------------------------------------------

#define NN    100000
#define NE    1600000
#define OUTD  64

typedef unsigned long long u64;

// ---------------- scratch (no allocations allowed) -------------------------
__device__ float g_fs[(size_t)NN * OUTD];     // 25.6 MB
__device__ float g_fd[(size_t)NN * OUTD];     // 25.6 MB
__device__ float g_logit[(size_t)NE * 4];     // 25.6 MB (reused as ex)
__device__ int   g_maxenc[NN * 4];            // 1.6 MB
__device__ float g_sum[NN * 4];               // 1.6 MB

// ---------------- helpers ---------------------------------------------------
__device__ __forceinline__ u64 pack2(float lo, float hi) {
    u64 r; asm("mov.b64 %0, {%1, %2};" : "=l"(r) : "f"(lo), "f"(hi)); return r;
}
__device__ __forceinline__ void fma2(u64& d, u64 a, u64 b) {
    asm("fma.rn.f32x2 %0, %1, %2, %0;" : "+l"(d) : "l"(a), "l"(b));
}
__device__ __forceinline__ float lo32(u64 v) { return __uint_as_float((unsigned)v); }
__device__ __forceinline__ float hi32(u64 v) { return __uint_as_float((unsigned)(v >> 32)); }

// order-preserving float->int encoding for atomic max
__device__ __forceinline__ int fenc(float f) {
    int i = __float_as_int(f);
    return i >= 0 ? i : (i ^ 0x7fffffff);
}
__device__ __forceinline__ float fdec(int e) {
    return __int_as_float(e >= 0 ? e : (e ^ 0x7fffffff));
}

__device__ __forceinline__ void red_add_v4(float* p, float a, float b, float c, float d) {
    asm volatile("red.global.add.v4.f32 [%0], {%1, %2, %3, %4};"
                 :: "l"(p), "f"(a), "f"(b), "f"(c), "f"(d) : "memory");
}
__device__ __forceinline__ void red_max_s32(int* p, int v) {
    asm volatile("red.global.max.s32 [%0], %1;" :: "l"(p), "r"(v) : "memory");
}

// ---------------- init ------------------------------------------------------
__global__ void k_init_rst(const float* __restrict__ bias, float* __restrict__ rst) {
    int i = blockIdx.x * 256 + threadIdx.x;          // NN*64 = 6.4M exactly
    rst[i] = bias[i & 63];
}
__global__ void k_init_seg() {
    int i = blockIdx.x * 256 + threadIdx.x;
    if (i < NN * 4) { g_maxenc[i] = 0x80000000; g_sum[i] = 0.0f; }
}

// ---------------- k_nodeproj ------------------------------------------------
// 512 thr = 16 warps, 8 nodes/warp (4 f32x2 node-pairs), 128 nodes/block.
// Combined W' = [Wsrc ; Wdst] -> 128 output cols; lane owns cols 4l..4l+3.
// smem: Wdup[128k][128c] u64 (128KB) + xs[16w][128k][4pair] u64 (64KB).
__global__ __launch_bounds__(512) void k_nodeproj(
    const float* __restrict__ nf, const float* __restrict__ Wsrc,
    const float* __restrict__ Wdst)
{
    extern __shared__ __align__(16) u64 sm[];
    u64* Wdup = sm;                  // 16384 u64
    u64* xs   = sm + 16384;          // 8192 u64
    int tid  = threadIdx.x;
    int warp = tid >> 5;
    int lane = tid & 31;
    int n0w  = blockIdx.x * 128 + warp * 8;

    for (int idx = tid; idx < 16384; idx += 512) {
        int k = idx >> 7, c = idx & 127;
        float w = (c < 64) ? Wsrc[c * 128 + k] : Wdst[(c - 64) * 128 + k];
        Wdup[idx] = pack2(w, w);
    }
    {   // stage xs: lane covers node n'=lane>>2, feature quarter q=lane&3
        int nl = lane >> 2, q = lane & 3;
        int nidx = min(n0w + nl, NN - 1);
        const float4* nfp = (const float4*)(nf + (size_t)nidx * 128 + q * 32);
        float* xf = (float*)(xs + warp * 512);
        int coff = ((nl >> 1) << 1) + (nl & 1);     // pair*2 + half
        #pragma unroll
        for (int i = 0; i < 8; i++) {
            float4 v = nfp[i];
            int kb = q * 32 + 4 * i;
            xf[(kb + 0) * 8 + coff] = v.x;
            xf[(kb + 1) * 8 + coff] = v.y;
            xf[(kb + 2) * 8 + coff] = v.z;
            xf[(kb + 3) * 8 + coff] = v.w;
        }
    }
    __syncthreads();

    u64 acc[4][4];                                  // [node-pair][col]
    #pragma unroll
    for (int p = 0; p < 4; p++)
        #pragma unroll
        for (int c = 0; c < 4; c++) acc[p][c] = 0ull;

    const u64* xp = xs + warp * 512;
    #pragma unroll 4
    for (int k = 0; k < 128; k++) {
        ulonglong2 wa = *(const ulonglong2*)(Wdup + k * 128 + 4 * lane);
        ulonglong2 wb = *(const ulonglong2*)(Wdup + k * 128 + 4 * lane + 2);
        ulonglong2 x0 = *(const ulonglong2*)(xp + k * 4);      // pairs 0,1
        ulonglong2 x1 = *(const ulonglong2*)(xp + k * 4 + 2);  // pairs 2,3
        fma2(acc[0][0], x0.x, wa.x); fma2(acc[0][1], x0.x, wa.y);
        fma2(acc[0][2], x0.x, wb.x); fma2(acc[0][3], x0.x, wb.y);
        fma2(acc[1][0], x0.y, wa.x); fma2(acc[1][1], x0.y, wa.y);
        fma2(acc[1][2], x0.y, wb.x); fma2(acc[1][3], x0.y, wb.y);
        fma2(acc[2][0], x1.x, wa.x); fma2(acc[2][1], x1.x, wa.y);
        fma2(acc[2][2], x1.x, wb.x); fma2(acc[2][3], x1.x, wb.y);
        fma2(acc[3][0], x1.y, wa.x); fma2(acc[3][1], x1.y, wa.y);
        fma2(acc[3][2], x1.y, wb.x); fma2(acc[3][3], x1.y, wb.y);
    }

    // store: lanes 0..15 -> g_fs cols 4l.., lanes 16..31 -> g_fd cols 4l-64..
    float* outb = (lane < 16) ? g_fs : g_fd;
    int cc0 = (4 * lane) & 63;
    #pragma unroll
    for (int p = 0; p < 4; p++) {
        int nlo = n0w + 2 * p;
        if (nlo < NN) {
            float4 v = make_float4(lo32(acc[p][0]), lo32(acc[p][1]),
                                   lo32(acc[p][2]), lo32(acc[p][3]));
            *(float4*)(outb + (size_t)nlo * 64 + cc0) = v;
        }
        if (nlo + 1 < NN) {
            float4 v = make_float4(hi32(acc[p][0]), hi32(acc[p][1]),
                                   hi32(acc[p][2]), hi32(acc[p][3]));
            *(float4*)(outb + (size_t)(nlo + 1) * 64 + cc0) = v;
        }
    }
}

// ---------------- k_edge ----------------------------------------------------
// 256 thr = 8 warps, 16 edges/warp (8 f32x2 edge-pairs), 128 edges/block.
// Lane owns cols 2l,2l+1.  Per k: 1 W LDS.128 + 4 x LDS.128 : 16 fma2.
__global__ __launch_bounds__(256) void k_edge(
    const float* __restrict__ ef, const float* __restrict__ We,
    const float* __restrict__ attn,
    const int* __restrict__ src, const int* __restrict__ dst)
{
    __shared__ __align__(16) u64 Wdup[32 * 64];    // [k][c] dup, 16 KB
    __shared__ __align__(16) u64 xs[8 * 32 * 8];   // [warp][k][edge-pair] 16 KB
    __shared__ float attns[64];

    int tid  = threadIdx.x;
    int warp = tid >> 5;
    int lane = tid & 31;
    int e0w  = blockIdx.x * 128 + warp * 16;

    for (int idx = tid; idx < 2048; idx += 256) {
        int k = idx >> 6, c = idx & 63;
        float w = We[c * 32 + k];
        Wdup[idx] = pack2(w, w);
    }
    if (tid < 64) attns[tid] = attn[tid];

    {   // stage xs: lane covers edge el=lane>>1, feature half hl=lane&1
        int el = lane >> 1, hl = lane & 1;
        const float4* efp = (const float4*)(ef + (size_t)(e0w + el) * 32 + hl * 16);
        float* xf = (float*)(xs + warp * 256);
        int coff = ((el >> 1) << 1) + (el & 1);     // ep*2 + half
        #pragma unroll
        for (int i = 0; i < 4; i++) {
            float4 v = efp[i];
            int kb = hl * 16 + 4 * i;
            xf[(kb + 0) * 16 + coff] = v.x;
            xf[(kb + 1) * 16 + coff] = v.y;
            xf[(kb + 2) * 16 + coff] = v.z;
            xf[(kb + 3) * 16 + coff] = v.w;
        }
    }
    int sreg = (lane < 16) ? src[e0w + lane] : dst[e0w + (lane - 16)];
    __syncthreads();

    u64 acc[8][2];                                  // [edge-pair][col lo/hi]
    #pragma unroll
    for (int p = 0; p < 8; p++) { acc[p][0] = 0ull; acc[p][1] = 0ull; }

    const u64* xp = xs + warp * 256;
    #pragma unroll
    for (int k = 0; k < 32; k++) {
        ulonglong2 wv = *(const ulonglong2*)(Wdup + k * 64 + 2 * lane);
        #pragma unroll
        for (int pp = 0; pp < 4; pp++) {
            ulonglong2 xv = *(const ulonglong2*)(xp + k * 8 + pp * 2);
            fma2(acc[2 * pp][0],     xv.x, wv.x);
            fma2(acc[2 * pp][1],     xv.x, wv.y);
            fma2(acc[2 * pp + 1][0], xv.y, wv.x);
            fma2(acc[2 * pp + 1][1], xv.y, wv.y);
        }
    }

    // epilogue: gather + leaky + attn-dot + 8-lane bfly reduce per head
    float a0 = attns[2 * lane], a1 = attns[2 * lane + 1];
    int hsel = lane >> 3;                           // head this lane's cols feed
    #pragma unroll
    for (int eb = 0; eb < 4; eb++) {
        int sv[4], dv[4];
        float2 fsv[4], fdv[4];
        #pragma unroll
        for (int i = 0; i < 4; i++) {
            int e = eb * 4 + i;
            sv[i] = __shfl_sync(0xffffffffu, sreg, e);
            dv[i] = __shfl_sync(0xffffffffu, sreg, 16 + e);
        }
        #pragma unroll
        for (int i = 0; i < 4; i++) {
            fsv[i] = *(const float2*)(g_fs + (size_t)sv[i] * 64 + 2 * lane);
            fdv[i] = *(const float2*)(g_fd + (size_t)dv[i] * 64 + 2 * lane);
        }
        #pragma unroll
        for (int i = 0; i < 4; i++) {
            int e = eb * 4 + i;
            int ep = e >> 1;
            float v0 = (e & 1) ? hi32(acc[ep][0]) : lo32(acc[ep][0]);
            float v1 = (e & 1) ? hi32(acc[ep][1]) : lo32(acc[ep][1]);
            float t0 = v0 + fsv[i].x + fdv[i].x;
            float t1 = v1 + fsv[i].y + fdv[i].y;
            t0 = fmaxf(t0, 0.2f * t0);
            t1 = fmaxf(t1, 0.2f * t1);
            float p = t0 * a0 + t1 * a1;
            p += __shfl_xor_sync(0xffffffffu, p, 1);
            p += __shfl_xor_sync(0xffffffffu, p, 2);
            p += __shfl_xor_sync(0xffffffffu, p, 4);
            if ((lane & 7) == 0) {
                g_logit[(size_t)(e0w + e) * 4 + hsel] = p;
                red_max_s32(&g_maxenc[dv[i] * 4 + hsel], fenc(p));
            }
        }
    }
}

// ---------------- k_soft ----------------------------------------------------
__global__ __launch_bounds__(256) void k_soft(const int* __restrict__ dst) {
    int e = blockIdx.x * 256 + threadIdx.x;
    int d = dst[e];
    float4 l = ((const float4*)g_logit)[e];
    int4 m = *(const int4*)(g_maxenc + d * 4);
    float4 ex;
    ex.x = __expf(l.x - fdec(m.x));
    ex.y = __expf(l.y - fdec(m.y));
    ex.z = __expf(l.z - fdec(m.z));
    ex.w = __expf(l.w - fdec(m.w));
    ((float4*)g_logit)[e] = ex;
    red_add_v4(g_sum + d * 4, ex.x, ex.y, ex.z, ex.w);
}

// ---------------- k_agg -----------------------------------------------------
// thread = (edge, head): 4x thread count for MLP over the L2 round-trips
__global__ __launch_bounds__(512) void k_agg(
    const int* __restrict__ src, const int* __restrict__ dst,
    float* __restrict__ rst, float* __restrict__ alpha_out)
{
    int idx = blockIdx.x * 512 + threadIdx.x;
    int e = idx >> 2, h = idx & 3;
    int s = src[e], d = dst[e];
    float ex  = g_logit[(size_t)e * 4 + h];
    float sum = g_sum[d * 4 + h];
    float al  = __fdividef(ex, sum);
    alpha_out[(size_t)e * 4 + h] = al;

    const float4* fsp = (const float4*)(g_fs + (size_t)s * 64 + h * 16);
    float* rrow = rst + (size_t)d * 64 + h * 16;
    #pragma unroll
    for (int i = 0; i < 4; i++) {
        float4 f = fsp[i];
        red_add_v4(rrow + 4 * i, f.x * al, f.y * al, f.z * al, f.w * al);
    }
}

// ---------------- launch ----------------------------------------------------
extern "C" void kernel_launch(void* const* d_in, const int* in_sizes, int n_in,
                              void* d_out, int out_size) {
    const float* node_feat = (const float*)d_in[0];
    const float* edge_feat = (const float*)d_in[1];
    const float* W_src     = (const float*)d_in[2];
    const float* W_dst     = (const float*)d_in[3];
    const float* W_edge    = (const float*)d_in[4];
    const float* attn      = (const float*)d_in[5];
    const float* bias      = (const float*)d_in[6];
    const int*   src       = (const int*)d_in[7];
    const int*   dst       = (const int*)d_in[8];
    float* rst   = (float*)d_out;                       // [N,64]
    float* alpha = (float*)d_out + (size_t)NN * OUTD;   // [E,4]

    const int NODE_SMEM = (16384 + 8192) * 8;           // 196608 B
    cudaFuncSetAttribute(k_nodeproj, cudaFuncAttributeMaxDynamicSharedMemorySize,
                         NODE_SMEM);

    k_init_rst<<<NN * 64 / 256, 256>>>(bias, rst);                      // 0
    k_init_seg<<<(NN * 4 + 255) / 256, 256>>>();                        // 1
    k_nodeproj<<<(NN + 127) / 128, 512, NODE_SMEM>>>(node_feat, W_src, W_dst); // 2
    k_edge<<<NE / 128, 256>>>(edge_feat, W_edge, attn, src, dst);       // 3
    k_soft<<<NE / 256, 256>>>(dst);                                     // 4
    k_agg<<<NE * 4 / 512, 512>>>(src, dst, rst, alpha);                 // 5
}

// round 7
// speedup vs baseline: 1.9992x; 1.0724x over previous
#include <cuda_runtime.h>
#include <cstdint>

// ---------------------------------------------------------------------------
// EdgeGATv2: N=100000 nodes, E=1600000 edges, IN=128, OUT=64 (H=4 x HD=16),
// EDGE_DIM=32.  Output = [rst (N*64 floats) ; alpha (E*4 floats)].
//
// R6: k_edge with 32 edges/warp (LDS:FMA2 = 12:32 -> fma-bound) and
// CSR pull-mode aggregation (kills all RED traffic to rst).
// ---------------------------------------------------------------------------

#define NN    100000
#define NE    1600000
#define OUTD  64
#define NB_SCAN 98          // ceil(NN/1024)

typedef unsigned long long u64;

// ---------------- scratch (no allocations allowed) -------------------------
__device__ float g_fs[(size_t)NN * OUTD];     // 25.6 MB
__device__ float g_fd[(size_t)NN * OUTD];     // 25.6 MB
__device__ float g_logit[(size_t)NE * 4];     // 25.6 MB (reused as ex)
__device__ int   g_maxenc[NN * 4];            // 1.6 MB
__device__ float g_sum[NN * 4];               // 1.6 MB
__device__ int   g_off[NN + 1];               // CSR row offsets
__device__ int   g_cur[NN];                   // degree, then scatter cursor
__device__ int   g_eid[NE];                   // CSR edge ids
__device__ int   g_part[NB_SCAN];             // scan partials
__device__ int   g_partoff[NB_SCAN];

// ---------------- helpers ---------------------------------------------------
__device__ __forceinline__ u64 pack2(float lo, float hi) {
    u64 r; asm("mov.b64 %0, {%1, %2};" : "=l"(r) : "f"(lo), "f"(hi)); return r;
}
__device__ __forceinline__ void fma2(u64& d, u64 a, u64 b) {
    asm("fma.rn.f32x2 %0, %1, %2, %0;" : "+l"(d) : "l"(a), "l"(b));
}
__device__ __forceinline__ float lo32(u64 v) { return __uint_as_float((unsigned)v); }
__device__ __forceinline__ float hi32(u64 v) { return __uint_as_float((unsigned)(v >> 32)); }

__device__ __forceinline__ int fenc(float f) {
    int i = __float_as_int(f);
    return i >= 0 ? i : (i ^ 0x7fffffff);
}
__device__ __forceinline__ float fdec(int e) {
    return __int_as_float(e >= 0 ? e : (e ^ 0x7fffffff));
}

__device__ __forceinline__ void red_add_v4(float* p, float a, float b, float c, float d) {
    asm volatile("red.global.add.v4.f32 [%0], {%1, %2, %3, %4};"
                 :: "l"(p), "f"(a), "f"(b), "f"(c), "f"(d) : "memory");
}
__device__ __forceinline__ void red_max_s32(int* p, int v) {
    asm volatile("red.global.max.s32 [%0], %1;" :: "l"(p), "r"(v) : "memory");
}

// ---------------- k_init_seg ------------------------------------------------
__global__ void k_init_seg() {
    int i = blockIdx.x * 256 + threadIdx.x;
    if (i < NN * 4) { g_maxenc[i] = 0x80000000; g_sum[i] = 0.0f; }
    if (i < NN) g_cur[i] = 0;
}

// ---------------- k_hist ----------------------------------------------------
__global__ void k_hist(const int* __restrict__ dst) {
    int e = blockIdx.x * 256 + threadIdx.x;
    atomicAdd(&g_cur[dst[e]], 1);
}

// ---------------- k_nodeproj (unchanged from R5) ---------------------------
__global__ __launch_bounds__(512) void k_nodeproj(
    const float* __restrict__ nf, const float* __restrict__ Wsrc,
    const float* __restrict__ Wdst)
{
    extern __shared__ __align__(16) u64 sm[];
    u64* Wdup = sm;                  // 16384 u64
    u64* xs   = sm + 16384;          // 8192 u64
    int tid  = threadIdx.x;
    int warp = tid >> 5;
    int lane = tid & 31;
    int n0w  = blockIdx.x * 128 + warp * 8;

    for (int idx = tid; idx < 16384; idx += 512) {
        int k = idx >> 7, c = idx & 127;
        float w = (c < 64) ? Wsrc[c * 128 + k] : Wdst[(c - 64) * 128 + k];
        Wdup[idx] = pack2(w, w);
    }
    {
        int nl = lane >> 2, q = lane & 3;
        int nidx = min(n0w + nl, NN - 1);
        const float4* nfp = (const float4*)(nf + (size_t)nidx * 128 + q * 32);
        float* xf = (float*)(xs + warp * 512);
        int coff = ((nl >> 1) << 1) + (nl & 1);
        #pragma unroll
        for (int i = 0; i < 8; i++) {
            float4 v = nfp[i];
            int kb = q * 32 + 4 * i;
            xf[(kb + 0) * 8 + coff] = v.x;
            xf[(kb + 1) * 8 + coff] = v.y;
            xf[(kb + 2) * 8 + coff] = v.z;
            xf[(kb + 3) * 8 + coff] = v.w;
        }
    }
    __syncthreads();

    u64 acc[4][4];
    #pragma unroll
    for (int p = 0; p < 4; p++)
        #pragma unroll
        for (int c = 0; c < 4; c++) acc[p][c] = 0ull;

    const u64* xp = xs + warp * 512;
    #pragma unroll 4
    for (int k = 0; k < 128; k++) {
        ulonglong2 wa = *(const ulonglong2*)(Wdup + k * 128 + 4 * lane);
        ulonglong2 wb = *(const ulonglong2*)(Wdup + k * 128 + 4 * lane + 2);
        ulonglong2 x0 = *(const ulonglong2*)(xp + k * 4);
        ulonglong2 x1 = *(const ulonglong2*)(xp + k * 4 + 2);
        fma2(acc[0][0], x0.x, wa.x); fma2(acc[0][1], x0.x, wa.y);
        fma2(acc[0][2], x0.x, wb.x); fma2(acc[0][3], x0.x, wb.y);
        fma2(acc[1][0], x0.y, wa.x); fma2(acc[1][1], x0.y, wa.y);
        fma2(acc[1][2], x0.y, wb.x); fma2(acc[1][3], x0.y, wb.y);
        fma2(acc[2][0], x1.x, wa.x); fma2(acc[2][1], x1.x, wa.y);
        fma2(acc[2][2], x1.x, wb.x); fma2(acc[2][3], x1.x, wb.y);
        fma2(acc[3][0], x1.y, wa.x); fma2(acc[3][1], x1.y, wa.y);
        fma2(acc[3][2], x1.y, wb.x); fma2(acc[3][3], x1.y, wb.y);
    }

    float* outb = (lane < 16) ? g_fs : g_fd;
    int cc0 = (4 * lane) & 63;
    #pragma unroll
    for (int p = 0; p < 4; p++) {
        int nlo = n0w + 2 * p;
        if (nlo < NN) {
            float4 v = make_float4(lo32(acc[p][0]), lo32(acc[p][1]),
                                   lo32(acc[p][2]), lo32(acc[p][3]));
            *(float4*)(outb + (size_t)nlo * 64 + cc0) = v;
        }
        if (nlo + 1 < NN) {
            float4 v = make_float4(hi32(acc[p][0]), hi32(acc[p][1]),
                                   hi32(acc[p][2]), hi32(acc[p][3]));
            *(float4*)(outb + (size_t)(nlo + 1) * 64 + cc0) = v;
        }
    }
}

// ---------------- k_edge v3 -------------------------------------------------
// 256 thr = 8 warps, 32 edges/warp (16 f32x2 edge-pairs), 256 edges/block.
// Lane owns cols 2l,2l+1.  Per k: 1 dense W LDS.128 + 8 broadcast x LDS.128
// : 32 fma2.  x-tile XOR pair-swizzle: slot(el,r) = 2*((el>>1)^(2*(r>>2)))
// + (el&1) -> write banks all distinct, read pairs stay u64-adjacent.
__global__ __launch_bounds__(256) void k_edge(
    const float* __restrict__ ef, const float* __restrict__ We,
    const float* __restrict__ attn,
    const int* __restrict__ src, const int* __restrict__ dst)
{
    extern __shared__ __align__(16) u64 esm[];
    u64*   Wdup  = esm;                     // 2048 u64 (16 KB) [k][c]
    u64*   xs    = esm + 2048;              // 8*512 u64 (32 KB)
    float* attns = (float*)(esm + 2048 + 4096);

    int tid  = threadIdx.x;
    int warp = tid >> 5;
    int lane = tid & 31;
    int e0w  = blockIdx.x * 256 + warp * 32;

    for (int idx = tid; idx < 2048; idx += 256) {
        int k = idx >> 6, c = idx & 63;
        float w = We[c * 32 + k];
        Wdup[idx] = pack2(w, w);
    }
    if (tid < 64) attns[tid] = attn[tid];

    {   // stage 32 edges x 32 feats, swizzled
        const float4* efg = (const float4*)ef + (size_t)e0w * 8;
        float* xf = (float*)(xs + warp * 512);
        #pragma unroll
        for (int it = 0; it < 8; it++) {
            int idx = it * 32 + lane;
            float4 v = efg[idx];
            int el = idx >> 3, j = idx & 7;
            int sl = 2 * ((el >> 1) ^ (2 * j)) + (el & 1);
            xf[(4 * j + 0) * 32 + sl] = v.x;
            xf[(4 * j + 1) * 32 + sl] = v.y;
            xf[(4 * j + 2) * 32 + sl] = v.z;
            xf[(4 * j + 3) * 32 + sl] = v.w;
        }
    }
    int sreg = src[e0w + lane];
    int dreg = dst[e0w + lane];
    __syncthreads();

    u64 acc[16][2];
    #pragma unroll
    for (int p = 0; p < 16; p++) { acc[p][0] = 0ull; acc[p][1] = 0ull; }

    const u64* xp = xs + warp * 512;
    #pragma unroll 2
    for (int k = 0; k < 32; k++) {
        ulonglong2 wv = *(const ulonglong2*)(Wdup + k * 64 + 2 * lane);
        int gk = 2 * (k >> 2);
        #pragma unroll
        for (int pp = 0; pp < 8; pp++) {
            ulonglong2 xv = *(const ulonglong2*)(xp + k * 16 + ((2 * pp) ^ gk));
            fma2(acc[2 * pp][0],     xv.x, wv.x);
            fma2(acc[2 * pp][1],     xv.x, wv.y);
            fma2(acc[2 * pp + 1][0], xv.y, wv.x);
            fma2(acc[2 * pp + 1][1], xv.y, wv.y);
        }
    }

    // epilogue: gather + leaky + attn-dot + 8-lane bfly reduce per head
    float a0 = attns[2 * lane], a1 = attns[2 * lane + 1];
    int hsel = lane >> 3;
    #pragma unroll
    for (int eb = 0; eb < 8; eb++) {
        int sv[4], dv[4];
        float2 fsv[4], fdv[4];
        #pragma unroll
        for (int i = 0; i < 4; i++) {
            int e = eb * 4 + i;
            sv[i] = __shfl_sync(0xffffffffu, sreg, e);
            dv[i] = __shfl_sync(0xffffffffu, dreg, e);
        }
        #pragma unroll
        for (int i = 0; i < 4; i++) {
            fsv[i] = *(const float2*)(g_fs + (size_t)sv[i] * 64 + 2 * lane);
            fdv[i] = *(const float2*)(g_fd + (size_t)dv[i] * 64 + 2 * lane);
        }
        #pragma unroll
        for (int i = 0; i < 4; i++) {
            int e = eb * 4 + i;
            int p = e >> 1;
            float v0 = (e & 1) ? hi32(acc[p][0]) : lo32(acc[p][0]);
            float v1 = (e & 1) ? hi32(acc[p][1]) : lo32(acc[p][1]);
            float t0 = v0 + fsv[i].x + fdv[i].x;
            float t1 = v1 + fsv[i].y + fdv[i].y;
            t0 = fmaxf(t0, 0.2f * t0);
            t1 = fmaxf(t1, 0.2f * t1);
            float pr = t0 * a0 + t1 * a1;
            pr += __shfl_xor_sync(0xffffffffu, pr, 1);
            pr += __shfl_xor_sync(0xffffffffu, pr, 2);
            pr += __shfl_xor_sync(0xffffffffu, pr, 4);
            if ((lane & 7) == 0) {
                g_logit[(size_t)(e0w + e) * 4 + hsel] = pr;
                red_max_s32(&g_maxenc[dv[i] * 4 + hsel], fenc(pr));
            }
        }
    }
}

// ---------------- CSR scan kernels -----------------------------------------
__global__ void k_scan1() {                     // per-1024-chunk partial sums
    __shared__ int red[256];
    int b = blockIdx.x, t = threadIdx.x;
    int s = 0;
    #pragma unroll
    for (int q = 0; q < 4; q++) {
        int idx = b * 1024 + q * 256 + t;
        if (idx < NN) s += g_cur[idx];
    }
    red[t] = s; __syncthreads();
    for (int o = 128; o > 0; o >>= 1) {
        if (t < o) red[t] += red[t + o];
        __syncthreads();
    }
    if (t == 0) g_part[b] = red[0];
}

__global__ void k_scan2() {                     // serial scan of 98 partials
    if (threadIdx.x == 0) {
        int run = 0;
        for (int b = 0; b < NB_SCAN; b++) { g_partoff[b] = run; run += g_part[b]; }
        g_off[NN] = run;
    }
}

__global__ __launch_bounds__(1024) void k_scan3() {  // intra-chunk excl scan
    __shared__ int sbuf[1024];
    int b = blockIdx.x, t = threadIdx.x;
    int i = b * 1024 + t;
    int v = (i < NN) ? g_cur[i] : 0;
    sbuf[t] = v; __syncthreads();
    #pragma unroll
    for (int o = 1; o < 1024; o <<= 1) {
        int x = (t >= o) ? sbuf[t - o] : 0;
        __syncthreads();
        sbuf[t] += x;
        __syncthreads();
    }
    if (i < NN) {
        int excl = g_partoff[b] + sbuf[t] - v;
        g_off[i] = excl;
        g_cur[i] = excl;                        // scatter cursor
    }
}

__global__ void k_scatter(const int* __restrict__ dst) {
    int e = blockIdx.x * 256 + threadIdx.x;
    int pos = atomicAdd(&g_cur[dst[e]], 1);
    g_eid[pos] = e;
}

// ---------------- k_soft ----------------------------------------------------
__global__ __launch_bounds__(256) void k_soft(const int* __restrict__ dst) {
    int e = blockIdx.x * 256 + threadIdx.x;
    int d = dst[e];
    float4 l = ((const float4*)g_logit)[e];
    int4 m = *(const int4*)(g_maxenc + d * 4);
    float4 ex;
    ex.x = __expf(l.x - fdec(m.x));
    ex.y = __expf(l.y - fdec(m.y));
    ex.z = __expf(l.z - fdec(m.z));
    ex.w = __expf(l.w - fdec(m.w));
    ((float4*)g_logit)[e] = ex;
    red_add_v4(g_sum + d * 4, ex.x, ex.y, ex.z, ex.w);
}

// ---------------- k_alpha ---------------------------------------------------
__global__ __launch_bounds__(256) void k_alpha(const int* __restrict__ dst,
                                               float* __restrict__ alpha_out) {
    int e = blockIdx.x * 256 + threadIdx.x;
    int d = dst[e];
    float4 ex = ((const float4*)g_logit)[e];
    float4 sm = *(const float4*)(g_sum + d * 4);
    float4 al;
    al.x = __fdividef(ex.x, sm.x);
    al.y = __fdividef(ex.y, sm.y);
    al.z = __fdividef(ex.z, sm.z);
    al.w = __fdividef(ex.w, sm.w);
    ((float4*)alpha_out)[e] = al;
}

// ---------------- k_pull (CSR aggregation, warp per dst) --------------------
__global__ __launch_bounds__(256) void k_pull(
    const int* __restrict__ src, const float* __restrict__ alpha,
    const float* __restrict__ bias, float* __restrict__ rst)
{
    int d = blockIdx.x * 8 + (threadIdx.x >> 5);     // NN divisible by 8
    int L = threadIdx.x & 31;
    int h = L >> 3;
    int row0 = g_off[d], row1 = g_off[d + 1];

    u64 acc = 0ull;
    for (int base = row0; base < row1; base += 32) {
        int n = min(32, row1 - base);
        int eidL = (base + L < row1) ? g_eid[base + L] : 0;
        int sL   = src[eidL];                        // parallel prefetch
        int i = 0;
        for (; i + 2 <= n; i += 2) {
            int e0 = __shfl_sync(0xffffffffu, eidL, i);
            int e1 = __shfl_sync(0xffffffffu, eidL, i + 1);
            int s0 = __shfl_sync(0xffffffffu, sL, i);
            int s1 = __shfl_sync(0xffffffffu, sL, i + 1);
            float al0 = alpha[(size_t)e0 * 4 + h];
            float al1 = alpha[(size_t)e1 * 4 + h];
            float2 f0 = *(const float2*)(g_fs + (size_t)s0 * 64 + 2 * L);
            float2 f1 = *(const float2*)(g_fs + (size_t)s1 * 64 + 2 * L);
            fma2(acc, pack2(al0, al0), pack2(f0.x, f0.y));
            fma2(acc, pack2(al1, al1), pack2(f1.x, f1.y));
        }
        if (i < n) {
            int e0 = __shfl_sync(0xffffffffu, eidL, i);
            int s0 = __shfl_sync(0xffffffffu, sL, i);
            float al0 = alpha[(size_t)e0 * 4 + h];
            float2 f0 = *(const float2*)(g_fs + (size_t)s0 * 64 + 2 * L);
            fma2(acc, pack2(al0, al0), pack2(f0.x, f0.y));
        }
    }
    float2 b2 = *(const float2*)(bias + 2 * L);
    float2 o = make_float2(lo32(acc) + b2.x, hi32(acc) + b2.y);
    *(float2*)(rst + (size_t)d * 64 + 2 * L) = o;
}

// ---------------- launch ----------------------------------------------------
extern "C" void kernel_launch(void* const* d_in, const int* in_sizes, int n_in,
                              void* d_out, int out_size) {
    const float* node_feat = (const float*)d_in[0];
    const float* edge_feat = (const float*)d_in[1];
    const float* W_src     = (const float*)d_in[2];
    const float* W_dst     = (const float*)d_in[3];
    const float* W_edge    = (const float*)d_in[4];
    const float* attn      = (const float*)d_in[5];
    const float* bias      = (const float*)d_in[6];
    const int*   src       = (const int*)d_in[7];
    const int*   dst       = (const int*)d_in[8];
    float* rst   = (float*)d_out;                       // [N,64]
    float* alpha = (float*)d_out + (size_t)NN * OUTD;   // [E,4]

    const int NODE_SMEM = (16384 + 8192) * 8;           // 196608 B
    const int EDGE_SMEM = (2048 + 4096) * 8 + 64 * 4;   // 49408 B
    cudaFuncSetAttribute(k_nodeproj, cudaFuncAttributeMaxDynamicSharedMemorySize,
                         NODE_SMEM);
    cudaFuncSetAttribute(k_edge, cudaFuncAttributeMaxDynamicSharedMemorySize,
                         EDGE_SMEM);

    k_init_seg<<<(NN * 4 + 255) / 256, 256>>>();                        // 0
    k_hist<<<NE / 256, 256>>>(dst);                                     // 1
    k_nodeproj<<<(NN + 127) / 128, 512, NODE_SMEM>>>(node_feat, W_src, W_dst); // 2
    k_edge<<<NE / 256, 256, EDGE_SMEM>>>(edge_feat, W_edge, attn, src, dst);   // 3
    k_scan1<<<NB_SCAN, 256>>>();                                        // 4
    k_scan2<<<1, 32>>>();                                               // 5
    k_scan3<<<NB_SCAN, 1024>>>();                                       // 6
    k_scatter<<<NE / 256, 256>>>(dst);                                  // 7
    k_soft<<<NE / 256, 256>>>(dst);                                     // 8
    k_alpha<<<NE / 256, 256>>>(dst, alpha);                             // 9
    k_pull<<<NN / 8, 256>>>(src, alpha, bias, rst);                     // 10
}